// round 11
// baseline (speedup 1.0000x reference)
#include <cuda_runtime.h>

// Contour_to_mask via winding angles.
// angle_k = acos(clip(dot/(|d||r|), ±(1-1e-5))) == clamp(atan2(|cr|,dot), A0, pi-A0)
// atan2(A,D), A,D>=0  ==  pi/4 + atan((A-D)/(A+D))   [exact rotation identity]
// => angle = pi/2 - copysign(min(pi/4 - atan(r), UMAX), dot)
// sign_k = tanh(K*cr);  out = min(|sum_k sign_k*angle_k|/2pi, 1)
//
// Coords prescaled by sqrt(K). 4 px/thread (two packed f32x2 pairs, same row).
// tanh fast path: tanh(cr) == copysign(1, cr) exactly when |cr| >= ~9.1 (fp32
// saturation). Warp-uniform __any_sync(|cr|<12) branch -> MUFU tanh only on
// ~0.15% of warp-iterations; results bit-identical to always-tanh.

#define MSIZE   256
#define KV      64
#define NCONT   8

#define SQRTK   316.2277660168379f
#define XSC     1.2352647109f          /* SQRTK / 256 */
#define TBAND   12.0f                  /* tanh saturation threshold (safe) */

typedef unsigned long long ull;

__device__ __forceinline__ ull pk(float lo, float hi) {
    ull r; asm("mov.b64 %0, {%1,%2};" : "=l"(r) : "f"(lo), "f"(hi)); return r;
}
__device__ __forceinline__ void upk(float& lo, float& hi, ull v) {
    asm("mov.b64 {%0,%1}, %2;" : "=f"(lo), "=f"(hi) : "l"(v));
}
__device__ __forceinline__ ull f2add(ull a, ull b) {
    ull d; asm("add.rn.f32x2 %0,%1,%2;" : "=l"(d) : "l"(a), "l"(b)); return d;
}
__device__ __forceinline__ ull f2mul(ull a, ull b) {
    ull d; asm("mul.rn.f32x2 %0,%1,%2;" : "=l"(d) : "l"(a), "l"(b)); return d;
}
__device__ __forceinline__ ull f2fma(ull a, ull b, ull c) {
    ull d; asm("fma.rn.f32x2 %0,%1,%2,%3;" : "=l"(d) : "l"(a), "l"(b), "l"(c)); return d;
}
__device__ __forceinline__ float frcp(float x) {
    float r; asm("rcp.approx.f32 %0,%1;" : "=f"(r) : "f"(x)); return r;
}
__device__ __forceinline__ float ftanh(float x) {
    float r; asm("tanh.approx.f32 %0,%1;" : "=f"(r) : "f"(x)); return r;
}

// atan deg-9 minimax on [-1,1] (odd): atan(r) ~= r*(p0 + p1 s + p2 s^2 + p3 s^3 + p4 s^4)
#define AP0  0.9998660f
#define AP1 -0.3302995f
#define AP2  0.1801410f
#define AP3 -0.0851330f
#define AP4  0.0208351f

#define QPI     0.7853981633974483f    /* pi/4 */
#define HPI     1.5707963267948966f
#define UMAX    1.5663241850f          /* pi/2 - acos(1-1e-5) */
#define INV2PI  0.15915494309189535f

__global__ void __launch_bounds__(128, 8) contour_mask_kernel(
    const float* __restrict__ contour,   // [NCONT, KV, 2]
    float* __restrict__ out)             // [NCONT, MSIZE, MSIZE]
{
    __shared__ float4 sv[KV];   // prescaled (X, X, Y, Y)

    const int c = blockIdx.y;
    const int t = threadIdx.x;

    if (t < KV) {
        const float2 v = ((const float2*)contour)[c * KV + t];
        const float X = v.x * SQRTK;
        const float Y = v.y * SQRTK;
        sv[t] = make_float4(X, X, Y, Y);
    }
    __syncthreads();

    const int gid  = blockIdx.x * blockDim.x + t;     // 0 .. 16383
    const int pix0 = gid * 4;
    const float xs = (float)(pix0 >> 8)  * XSC;
    const float yb = (float)(pix0 & 255) * XSC;
    const ull negxp  = pk(-xs, -xs);
    const ull negy01 = pk(-yb, -(yb + XSC));
    const ull negy23 = pk(-(yb + 2.0f * XSC), -(yb + 3.0f * XSC));

    const ull P0 = pk(AP0, AP0), P1 = pk(AP1, AP1), P2 = pk(AP2, AP2);
    const ull P3 = pk(AP3, AP3), P4 = pk(AP4, AP4);
    const ull MNEG1 = pk(-1.0f, -1.0f);
    const ull QP2   = pk(QPI, QPI);

    // k = 0 state
    float4 q0 = sv[0];
    ull dxp  = f2add(*(const ull*)&q0.x, negxp);
    ull ndxp = f2mul(dxp, MNEG1);
    ull dy01 = f2add(*(const ull*)&q0.z, negy01);
    ull dy23 = f2add(*(const ull*)&q0.z, negy23);

    float S1[4] = {0.f, 0.f, 0.f, 0.f};   // sum t*cs per pixel
    float St[4] = {0.f, 0.f, 0.f, 0.f};   // sum t per pixel

#pragma unroll 4
    for (int k = 0; k < KV; k++) {
        const int kn = (k + 1) & (KV - 1);
        const float4 q = sv[kn];                    // LDS.128 broadcast
        const ull rxp  = f2add(*(const ull*)&q.x, negxp);
        const ull nrxp = f2mul(rxp, MNEG1);
        const ull ry01 = f2add(*(const ull*)&q.z, negy01);
        const ull ry23 = f2add(*(const ull*)&q.z, negy23);

        const ull drs  = f2mul(dxp, rxp);           // (dx*rx, dx*rx)

        const ull dot01 = f2fma(dy01, ry01, drs);
        const ull dot23 = f2fma(dy23, ry23, drs);
        const ull cr01  = f2fma(dy01, rxp, f2mul(ndxp, ry01));
        const ull cr23  = f2fma(dy23, rxp, f2mul(ndxp, ry23));

        float cr[4], dd[4];
        upk(cr[0], cr[1], cr01); upk(cr[2], cr[3], cr23);
        upk(dd[0], dd[1], dot01); upk(dd[2], dd[3], dot23);

        // sign factor: tanh(cr) == copysign(1,cr) exactly outside |cr|<~9.1.
        // Warp-uniform slow path only when some lane is in the band.
        float tt[4];
        const float mincr = fminf(fminf(fabsf(cr[0]), fabsf(cr[1])),
                                  fminf(fabsf(cr[2]), fabsf(cr[3])));
        if (__any_sync(0xffffffffu, mincr < TBAND)) {
#pragma unroll
            for (int j = 0; j < 4; j++) tt[j] = ftanh(cr[j]);
        } else {
#pragma unroll
            for (int j = 0; j < 4; j++)
                tt[j] = __int_as_float(0x3f800000u |
                                       (__float_as_int(cr[j]) & 0x80000000u));
        }

        float rr[4];
#pragma unroll
        for (int j = 0; j < 4; j++) {
            const float num = fabsf(cr[j]) - fabsf(dd[j]);
            const float den = fabsf(cr[j]) + fabsf(dd[j]);
            rr[j] = num * frcp(den);                 // in [-1, 1]
        }

        // packed atan poly (odd): at = r * poly(r*r); w = pi/4 - at >= 0
        const ull r01 = pk(rr[0], rr[1]);
        const ull r23 = pk(rr[2], rr[3]);
        const ull s01 = f2mul(r01, r01);
        const ull s23 = f2mul(r23, r23);
        ull p01 = f2fma(s01, P4, P3);
        ull p23 = f2fma(s23, P4, P3);
        p01 = f2fma(p01, s01, P2);  p23 = f2fma(p23, s23, P2);
        p01 = f2fma(p01, s01, P1);  p23 = f2fma(p23, s23, P1);
        p01 = f2fma(p01, s01, P0);  p23 = f2fma(p23, s23, P0);
        const ull at01 = f2mul(p01, r01);
        const ull at23 = f2mul(p23, r23);
        const ull w01 = f2fma(at01, MNEG1, QP2);
        const ull w23 = f2fma(at23, MNEG1, QP2);

        float ww[4];
        upk(ww[0], ww[1], w01); upk(ww[2], ww[3], w23);

#pragma unroll
        for (int j = 0; j < 4; j++) {
            const float u = fminf(ww[j], UMAX);
            const float cs = __int_as_float(__float_as_int(u) |
                                            (__float_as_int(dd[j]) & 0x80000000u));
            S1[j] = fmaf(tt[j], cs, S1[j]);
            St[j] += tt[j];
        }

        // rotate (register renames only)
        dxp = rxp; ndxp = nrxp; dy01 = ry01; dy23 = ry23;
    }

    float4 o;
    o.x = fminf(fabsf(fmaf(HPI, St[0], -S1[0])) * INV2PI, 1.0f);
    o.y = fminf(fabsf(fmaf(HPI, St[1], -S1[1])) * INV2PI, 1.0f);
    o.z = fminf(fabsf(fmaf(HPI, St[2], -S1[2])) * INV2PI, 1.0f);
    o.w = fminf(fabsf(fmaf(HPI, St[3], -S1[3])) * INV2PI, 1.0f);
    ((float4*)out)[c * (MSIZE * MSIZE / 4) + gid] = o;
}

extern "C" void kernel_launch(void* const* d_in, const int* in_sizes, int n_in,
                              void* d_out, int out_size)
{
    const float* contour = (const float*)d_in[0];
    float* out = (float*)d_out;

    dim3 grid((MSIZE * MSIZE) / (4 * 128), NCONT);   // 128 x 8 = 1024 blocks
    contour_mask_kernel<<<grid, 128>>>(contour, out);
}

// round 12
// speedup vs baseline: 1.0650x; 1.0650x over previous
#include <cuda_runtime.h>

// Contour_to_mask via winding angles.
// angle_k = acos(clip(dot/(|d||r|))) ~= atan2(|cr|,dot) = pi/4 + atan((A-D)/(A+D))
// => angle = pi/2 - copysign(pi/4 - atan(r), dot)      (UMAX clip dropped: err<=0.0045
//    rad only on terms where ref's +-(1-1e-5) clip binds; negligible in output)
// sign_k = tanh(K*cr);  out = min(|sum_k sign_k*angle_k|/2pi, 1)
//
// Coords prescaled by sqrt(K). 4 px/thread (two packed f32x2 pairs, same row);
// vertex LDS.128 + rx prep + dx*rx shared across the 4 pixels.

#define MSIZE   256
#define KV      64
#define NCONT   8

#define SQRTK   316.2277660168379f
#define XSC     1.2352647109f          /* SQRTK / 256 */

typedef unsigned long long ull;

__device__ __forceinline__ ull pk(float lo, float hi) {
    ull r; asm("mov.b64 %0, {%1,%2};" : "=l"(r) : "f"(lo), "f"(hi)); return r;
}
__device__ __forceinline__ void upk(float& lo, float& hi, ull v) {
    asm("mov.b64 {%0,%1}, %2;" : "=f"(lo), "=f"(hi) : "l"(v));
}
__device__ __forceinline__ ull f2add(ull a, ull b) {
    ull d; asm("add.rn.f32x2 %0,%1,%2;" : "=l"(d) : "l"(a), "l"(b)); return d;
}
__device__ __forceinline__ ull f2mul(ull a, ull b) {
    ull d; asm("mul.rn.f32x2 %0,%1,%2;" : "=l"(d) : "l"(a), "l"(b)); return d;
}
__device__ __forceinline__ ull f2fma(ull a, ull b, ull c) {
    ull d; asm("fma.rn.f32x2 %0,%1,%2,%3;" : "=l"(d) : "l"(a), "l"(b), "l"(c)); return d;
}
__device__ __forceinline__ float frcp(float x) {
    float r; asm("rcp.approx.f32 %0,%1;" : "=f"(r) : "f"(x)); return r;
}
__device__ __forceinline__ float ftanh(float x) {
    float r; asm("tanh.approx.f32 %0,%1;" : "=f"(r) : "f"(x)); return r;
}

// atan deg-7 minimax on [-1,1] (odd): atan(r) ~= r*(b0 + b1 s + b2 s^2 + b3 s^3)
// max err ~1.2e-4 rad
#define BP0  0.9992150f
#define BP1 -0.3211819f
#define BP2  0.1462766f
#define BP3 -0.0389929f

#define QPI     0.7853981633974483f    /* pi/4 */
#define HPI     1.5707963267948966f
#define INV2PI  0.15915494309189535f

__global__ void __launch_bounds__(128, 8) contour_mask_kernel(
    const float* __restrict__ contour,   // [NCONT, KV, 2]
    float* __restrict__ out)             // [NCONT, MSIZE, MSIZE]
{
    __shared__ float4 sv[KV];   // prescaled (X, X, Y, Y)

    const int c = blockIdx.y;
    const int t = threadIdx.x;

    if (t < KV) {
        const float2 v = ((const float2*)contour)[c * KV + t];
        const float X = v.x * SQRTK;
        const float Y = v.y * SQRTK;
        sv[t] = make_float4(X, X, Y, Y);
    }
    __syncthreads();

    const int gid  = blockIdx.x * blockDim.x + t;     // 0 .. 16383
    const int pix0 = gid * 4;
    const float xs = (float)(pix0 >> 8)  * XSC;
    const float yb = (float)(pix0 & 255) * XSC;
    const ull negxp  = pk(-xs, -xs);
    const ull negy01 = pk(-yb, -(yb + XSC));
    const ull negy23 = pk(-(yb + 2.0f * XSC), -(yb + 3.0f * XSC));

    const ull B0 = pk(BP0, BP0), B1 = pk(BP1, BP1);
    const ull B2 = pk(BP2, BP2), B3 = pk(BP3, BP3);
    const ull MNEG1 = pk(-1.0f, -1.0f);
    const ull QP2   = pk(QPI, QPI);

    // k = 0 state
    float4 q0 = sv[0];
    ull dxp  = f2add(*(const ull*)&q0.x, negxp);
    ull ndxp = f2mul(dxp, MNEG1);
    ull dy01 = f2add(*(const ull*)&q0.z, negy01);
    ull dy23 = f2add(*(const ull*)&q0.z, negy23);

    float S1[4] = {0.f, 0.f, 0.f, 0.f};   // sum t*cs per pixel
    float St[4] = {0.f, 0.f, 0.f, 0.f};   // sum t per pixel

#pragma unroll 4
    for (int k = 0; k < KV; k++) {
        const int kn = (k + 1) & (KV - 1);
        const float4 q = sv[kn];                    // LDS.128 broadcast
        const ull rxp  = f2add(*(const ull*)&q.x, negxp);
        const ull nrxp = f2mul(rxp, MNEG1);
        const ull ry01 = f2add(*(const ull*)&q.z, negy01);
        const ull ry23 = f2add(*(const ull*)&q.z, negy23);

        const ull drs  = f2mul(dxp, rxp);           // (dx*rx, dx*rx)

        const ull dot01 = f2fma(dy01, ry01, drs);
        const ull dot23 = f2fma(dy23, ry23, drs);
        const ull cr01  = f2fma(dy01, rxp, f2mul(ndxp, ry01));
        const ull cr23  = f2fma(dy23, rxp, f2mul(ndxp, ry23));

        float cr[4], dd[4];
        upk(cr[0], cr[1], cr01); upk(cr[2], cr[3], cr23);
        upk(dd[0], dd[1], dot01); upk(dd[2], dd[3], dot23);

        float rr[4], tt[4];
#pragma unroll
        for (int j = 0; j < 4; j++) {
            tt[j] = ftanh(cr[j]);                    // == tanh(K*cross)
            const float num = fabsf(cr[j]) - fabsf(dd[j]);
            const float den = fabsf(cr[j]) + fabsf(dd[j]);
            rr[j] = num * frcp(den);                 // in [-1, 1]
        }

        // packed atan poly (odd, deg 7): at = r * poly(r*r); w = pi/4 - at >= 0
        const ull r01 = pk(rr[0], rr[1]);
        const ull r23 = pk(rr[2], rr[3]);
        const ull s01 = f2mul(r01, r01);
        const ull s23 = f2mul(r23, r23);
        ull p01 = f2fma(s01, B3, B2);
        ull p23 = f2fma(s23, B3, B2);
        p01 = f2fma(p01, s01, B1);  p23 = f2fma(p23, s23, B1);
        p01 = f2fma(p01, s01, B0);  p23 = f2fma(p23, s23, B0);
        const ull at01 = f2mul(p01, r01);
        const ull at23 = f2mul(p23, r23);
        const ull w01 = f2fma(at01, MNEG1, QP2);
        const ull w23 = f2fma(at23, MNEG1, QP2);

        float ww[4];
        upk(ww[0], ww[1], w01); upk(ww[2], ww[3], w23);

#pragma unroll
        for (int j = 0; j < 4; j++) {
            // cs = copysign(w, dot);  angle = pi/2 - cs   (no UMAX clip)
            const float cs = __int_as_float(__float_as_int(ww[j]) |
                                            (__float_as_int(dd[j]) & 0x80000000u));
            S1[j] = fmaf(tt[j], cs, S1[j]);
            St[j] += tt[j];
        }

        // rotate (register renames only)
        dxp = rxp; ndxp = nrxp; dy01 = ry01; dy23 = ry23;
    }

    float4 o;
    o.x = fminf(fabsf(fmaf(HPI, St[0], -S1[0])) * INV2PI, 1.0f);
    o.y = fminf(fabsf(fmaf(HPI, St[1], -S1[1])) * INV2PI, 1.0f);
    o.z = fminf(fabsf(fmaf(HPI, St[2], -S1[2])) * INV2PI, 1.0f);
    o.w = fminf(fabsf(fmaf(HPI, St[3], -S1[3])) * INV2PI, 1.0f);
    ((float4*)out)[c * (MSIZE * MSIZE / 4) + gid] = o;
}

extern "C" void kernel_launch(void* const* d_in, const int* in_sizes, int n_in,
                              void* d_out, int out_size)
{
    const float* contour = (const float*)d_in[0];
    float* out = (float*)d_out;

    dim3 grid((MSIZE * MSIZE) / (4 * 128), NCONT);   // 128 x 8 = 1024 blocks
    contour_mask_kernel<<<grid, 128>>>(contour, out);
}

// round 13
// speedup vs baseline: 1.0749x; 1.0092x over previous
#include <cuda_runtime.h>

// Contour_to_mask via winding angles.
// angle_k = acos(clip(dot/(|d||r|))) ~= atan2(|cr|,dot) = pi/4 + atan((A-D)/(A+D))
// => angle = pi/2 - copysign(pi/4 - atan(r), dot)
// sign_k = tanh(K*cr);  out = min(|sum_k sign_k*angle_k|/2pi, 1)
//
// Coords prescaled by sqrt(K). 4 px/thread (two packed f32x2 pairs, same row).
// EDGE SPLIT: 256-thd block covers 512 px; threads 0-127 do edges 0-31,
// threads 128-255 do edges 32-63 for the same pixels; merged via smem.
// Doubles resident warps (latency hiding) at identical total slot count.

#define MSIZE   256
#define KV      64
#define NCONT   8

#define SQRTK   316.2277660168379f
#define XSC     1.2352647109f          /* SQRTK / 256 */

typedef unsigned long long ull;

__device__ __forceinline__ ull pk(float lo, float hi) {
    ull r; asm("mov.b64 %0, {%1,%2};" : "=l"(r) : "f"(lo), "f"(hi)); return r;
}
__device__ __forceinline__ void upk(float& lo, float& hi, ull v) {
    asm("mov.b64 {%0,%1}, %2;" : "=f"(lo), "=f"(hi) : "l"(v));
}
__device__ __forceinline__ ull f2add(ull a, ull b) {
    ull d; asm("add.rn.f32x2 %0,%1,%2;" : "=l"(d) : "l"(a), "l"(b)); return d;
}
__device__ __forceinline__ ull f2mul(ull a, ull b) {
    ull d; asm("mul.rn.f32x2 %0,%1,%2;" : "=l"(d) : "l"(a), "l"(b)); return d;
}
__device__ __forceinline__ ull f2fma(ull a, ull b, ull c) {
    ull d; asm("fma.rn.f32x2 %0,%1,%2,%3;" : "=l"(d) : "l"(a), "l"(b), "l"(c)); return d;
}
__device__ __forceinline__ float frcp(float x) {
    float r; asm("rcp.approx.f32 %0,%1;" : "=f"(r) : "f"(x)); return r;
}
__device__ __forceinline__ float ftanh(float x) {
    float r; asm("tanh.approx.f32 %0,%1;" : "=f"(r) : "f"(x)); return r;
}

// atan deg-7 minimax on [-1,1] (odd): atan(r) ~= r*(b0 + b1 s + b2 s^2 + b3 s^3)
#define BP0  0.9992150f
#define BP1 -0.3211819f
#define BP2  0.1462766f
#define BP3 -0.0389929f

#define QPI     0.7853981633974483f    /* pi/4 */
#define HPI     1.5707963267948966f
#define INV2PI  0.15915494309189535f

__global__ void __launch_bounds__(256, 4) contour_mask_kernel(
    const float* __restrict__ contour,   // [NCONT, KV, 2]
    float* __restrict__ out)             // [NCONT, MSIZE, MSIZE]
{
    __shared__ float4 sv[KV];    // prescaled (X, X, Y, Y)
    __shared__ float4 sm1[128];  // partial S1 from upper half
    __shared__ float4 smt[128];  // partial St from upper half

    const int c  = blockIdx.y;
    const int t  = threadIdx.x;
    const int h  = t >> 7;        // edge half: 0 -> edges 0-31, 1 -> 32-63
    const int tl = t & 127;       // pixel-group lane within block

    if (t < KV) {
        const float2 v = ((const float2*)contour)[c * KV + t];
        const float X = v.x * SQRTK;
        const float Y = v.y * SQRTK;
        sv[t] = make_float4(X, X, Y, Y);
    }
    __syncthreads();

    const int gpx  = blockIdx.x * 128 + tl;           // pixel group 0..16383
    const int pix0 = gpx * 4;
    const float xs = (float)(pix0 >> 8)  * XSC;
    const float yb = (float)(pix0 & 255) * XSC;
    const ull negxp  = pk(-xs, -xs);
    const ull negy01 = pk(-yb, -(yb + XSC));
    const ull negy23 = pk(-(yb + 2.0f * XSC), -(yb + 3.0f * XSC));

    const ull B0 = pk(BP0, BP0), B1 = pk(BP1, BP1);
    const ull B2 = pk(BP2, BP2), B3 = pk(BP3, BP3);
    const ull MNEG1 = pk(-1.0f, -1.0f);
    const ull QP2   = pk(QPI, QPI);

    // starting vertex for this half
    const int k0 = h << 5;
    float4 q0 = sv[k0];
    ull dxp  = f2add(*(const ull*)&q0.x, negxp);
    ull ndxp = f2mul(dxp, MNEG1);
    ull dy01 = f2add(*(const ull*)&q0.z, negy01);
    ull dy23 = f2add(*(const ull*)&q0.z, negy23);

    float S1[4] = {0.f, 0.f, 0.f, 0.f};   // sum t*cs per pixel
    float St[4] = {0.f, 0.f, 0.f, 0.f};   // sum t per pixel

#pragma unroll 4
    for (int i = 0; i < 32; i++) {
        const int kn = (k0 + i + 1) & (KV - 1);
        const float4 q = sv[kn];                    // LDS.128 broadcast
        const ull rxp  = f2add(*(const ull*)&q.x, negxp);
        const ull nrxp = f2mul(rxp, MNEG1);
        const ull ry01 = f2add(*(const ull*)&q.z, negy01);
        const ull ry23 = f2add(*(const ull*)&q.z, negy23);

        const ull drs  = f2mul(dxp, rxp);           // (dx*rx, dx*rx)

        const ull dot01 = f2fma(dy01, ry01, drs);
        const ull dot23 = f2fma(dy23, ry23, drs);
        const ull cr01  = f2fma(dy01, rxp, f2mul(ndxp, ry01));
        const ull cr23  = f2fma(dy23, rxp, f2mul(ndxp, ry23));

        float cr[4], dd[4];
        upk(cr[0], cr[1], cr01); upk(cr[2], cr[3], cr23);
        upk(dd[0], dd[1], dot01); upk(dd[2], dd[3], dot23);

        float rr[4], tt[4];
#pragma unroll
        for (int j = 0; j < 4; j++) {
            tt[j] = ftanh(cr[j]);                    // == tanh(K*cross)
            const float num = fabsf(cr[j]) - fabsf(dd[j]);
            const float den = fabsf(cr[j]) + fabsf(dd[j]);
            rr[j] = num * frcp(den);                 // in [-1, 1]
        }

        // packed atan poly (odd, deg 7): at = r * poly(r*r); w = pi/4 - at >= 0
        const ull r01 = pk(rr[0], rr[1]);
        const ull r23 = pk(rr[2], rr[3]);
        const ull s01 = f2mul(r01, r01);
        const ull s23 = f2mul(r23, r23);
        ull p01 = f2fma(s01, B3, B2);
        ull p23 = f2fma(s23, B3, B2);
        p01 = f2fma(p01, s01, B1);  p23 = f2fma(p23, s23, B1);
        p01 = f2fma(p01, s01, B0);  p23 = f2fma(p23, s23, B0);
        const ull at01 = f2mul(p01, r01);
        const ull at23 = f2mul(p23, r23);
        const ull w01 = f2fma(at01, MNEG1, QP2);
        const ull w23 = f2fma(at23, MNEG1, QP2);

        float ww[4];
        upk(ww[0], ww[1], w01); upk(ww[2], ww[3], w23);

#pragma unroll
        for (int j = 0; j < 4; j++) {
            // cs = copysign(w, dot);  angle = pi/2 - cs
            const float cs = __int_as_float(__float_as_int(ww[j]) |
                                            (__float_as_int(dd[j]) & 0x80000000u));
            S1[j] = fmaf(tt[j], cs, S1[j]);
            St[j] += tt[j];
        }

        // rotate (register renames only)
        dxp = rxp; ndxp = nrxp; dy01 = ry01; dy23 = ry23;
    }

    // merge halves via smem
    if (h) {
        sm1[tl] = make_float4(S1[0], S1[1], S1[2], S1[3]);
        smt[tl] = make_float4(St[0], St[1], St[2], St[3]);
    }
    __syncthreads();
    if (!h) {
        const float4 p1 = sm1[tl];
        const float4 pt = smt[tl];
        const float s1x = S1[0] + p1.x, stx = St[0] + pt.x;
        const float s1y = S1[1] + p1.y, sty = St[1] + pt.y;
        const float s1z = S1[2] + p1.z, stz = St[2] + pt.z;
        const float s1w = S1[3] + p1.w, stw = St[3] + pt.w;

        float4 o;
        o.x = fminf(fabsf(fmaf(HPI, stx, -s1x)) * INV2PI, 1.0f);
        o.y = fminf(fabsf(fmaf(HPI, sty, -s1y)) * INV2PI, 1.0f);
        o.z = fminf(fabsf(fmaf(HPI, stz, -s1z)) * INV2PI, 1.0f);
        o.w = fminf(fabsf(fmaf(HPI, stw, -s1w)) * INV2PI, 1.0f);
        ((float4*)out)[c * (MSIZE * MSIZE / 4) + gpx] = o;
    }
}

extern "C" void kernel_launch(void* const* d_in, const int* in_sizes, int n_in,
                              void* d_out, int out_size)
{
    const float* contour = (const float*)d_in[0];
    float* out = (float*)d_out;

    dim3 grid((MSIZE * MSIZE) / 512, NCONT);   // 128 x 8 = 1024 blocks, 256 thd
    contour_mask_kernel<<<grid, 256>>>(contour, out);
}

// round 14
// speedup vs baseline: 1.1491x; 1.0691x over previous
#include <cuda_runtime.h>

// Contour_to_mask via winding angles.
// angle_k = acos(clip(dot/(|d||r|))) ~= atan2(|cr|,dot) = pi/4 + atan((A-D)/(A+D))
// => angle = pi/2 - copysign(pi/4 - atan(r), dot)
// sign_k = tanh(K*cr);  out = min(|sum_k sign_k*angle_k|/2pi, 1)
//
// Coords prescaled by sqrt(K). 4 px/thread, FULLY SCALAR body:
// poly coefficients as immediates (FFMA-imm, rt_SMSP=1), abs via operand
// modifiers, no packed f32x2 (packed ops cost rt=3 via register-bank rule
// and force pk/upk MOV traffic).

#define MSIZE   256
#define KV      64
#define NCONT   8

#define SQRTK   316.2277660168379f
#define XSC     1.2352647109f          /* SQRTK / 256 */

__device__ __forceinline__ float frcp(float x) {
    float r; asm("rcp.approx.f32 %0,%1;" : "=f"(r) : "f"(x)); return r;
}
__device__ __forceinline__ float ftanh(float x) {
    float r; asm("tanh.approx.f32 %0,%1;" : "=f"(r) : "f"(x)); return r;
}

// atan deg-7 minimax on [-1,1] (odd): atan(r) ~= r*(b0 + b1 s + b2 s^2 + b3 s^3)
#define BP0  0.9992150f
#define BP1 -0.3211819f
#define BP2  0.1462766f
#define BP3 -0.0389929f

#define QPI     0.7853981633974483f    /* pi/4 */
#define HPI     1.5707963267948966f
#define INV2PI  0.15915494309189535f

__global__ void __launch_bounds__(128, 8) contour_mask_kernel(
    const float* __restrict__ contour,   // [NCONT, KV, 2]
    float* __restrict__ out)             // [NCONT, MSIZE, MSIZE]
{
    __shared__ float2 sv[KV];   // prescaled (X, Y)

    const int c = blockIdx.y;
    const int t = threadIdx.x;

    if (t < KV) {
        const float2 v = ((const float2*)contour)[c * KV + t];
        sv[t] = make_float2(v.x * SQRTK, v.y * SQRTK);
    }
    __syncthreads();

    const int gid  = blockIdx.x * blockDim.x + t;     // 0 .. 16383
    const int pix0 = gid * 4;
    const float xs = (float)(pix0 >> 8)  * XSC;
    const float yb = (float)(pix0 & 255) * XSC;
    const float ys0 = yb;
    const float ys1 = yb + XSC;
    const float ys2 = yb + 2.0f * XSC;
    const float ys3 = yb + 3.0f * XSC;

    // k = 0 state
    const float2 v0 = sv[0];
    float dx  = v0.x - xs;
    float dy0 = v0.y - ys0;
    float dy1 = v0.y - ys1;
    float dy2 = v0.y - ys2;
    float dy3 = v0.y - ys3;

    float S10 = 0.f, S11 = 0.f, S12 = 0.f, S13 = 0.f;   // sum t*cs
    float St0 = 0.f, St1 = 0.f, St2 = 0.f, St3 = 0.f;   // sum t

#pragma unroll 4
    for (int k = 0; k < KV; k++) {
        const int kn = (k + 1) & (KV - 1);
        const float2 q = sv[kn];                     // LDS.64 broadcast
        const float rx  = q.x - xs;
        const float ry0 = q.y - ys0;
        const float ry1 = q.y - ys1;
        const float ry2 = q.y - ys2;
        const float ry3 = q.y - ys3;

        const float drs = dx * rx;                   // shared across 4 px

        const float dd0 = fmaf(dy0, ry0, drs);
        const float dd1 = fmaf(dy1, ry1, drs);
        const float dd2 = fmaf(dy2, ry2, drs);
        const float dd3 = fmaf(dy3, ry3, drs);

        const float cr0 = fmaf(dy0, rx, -(dx * ry0));
        const float cr1 = fmaf(dy1, rx, -(dx * ry1));
        const float cr2 = fmaf(dy2, rx, -(dx * ry2));
        const float cr3 = fmaf(dy3, rx, -(dx * ry3));

        const float t0 = ftanh(cr0);                 // == tanh(K*cross)
        const float t1 = ftanh(cr1);
        const float t2 = ftanh(cr2);
        const float t3 = ftanh(cr3);

        // r = (|cr| - |dd|) / (|cr| + |dd|)  in [-1, 1]  (abs = operand mods)
        const float r0 = (fabsf(cr0) - fabsf(dd0)) * frcp(fabsf(cr0) + fabsf(dd0));
        const float r1 = (fabsf(cr1) - fabsf(dd1)) * frcp(fabsf(cr1) + fabsf(dd1));
        const float r2 = (fabsf(cr2) - fabsf(dd2)) * frcp(fabsf(cr2) + fabsf(dd2));
        const float r3 = (fabsf(cr3) - fabsf(dd3)) * frcp(fabsf(cr3) + fabsf(dd3));

        // scalar atan poly deg-7, immediate coefficients (FFMA-imm rt=1)
        const float s0 = r0 * r0, s1 = r1 * r1, s2 = r2 * r2, s3 = r3 * r3;
        float p0 = fmaf(s0, BP3, BP2);
        float p1 = fmaf(s1, BP3, BP2);
        float p2 = fmaf(s2, BP3, BP2);
        float p3 = fmaf(s3, BP3, BP2);
        p0 = fmaf(p0, s0, BP1);  p1 = fmaf(p1, s1, BP1);
        p2 = fmaf(p2, s2, BP1);  p3 = fmaf(p3, s3, BP1);
        p0 = fmaf(p0, s0, BP0);  p1 = fmaf(p1, s1, BP0);
        p2 = fmaf(p2, s2, BP0);  p3 = fmaf(p3, s3, BP0);

        // w = pi/4 - r*poly >= 0  (single FFMA with negated product)
        const float w0 = fmaf(-r0, p0, QPI);
        const float w1 = fmaf(-r1, p1, QPI);
        const float w2 = fmaf(-r2, p2, QPI);
        const float w3 = fmaf(-r3, p3, QPI);

        // cs = copysign(w, dot);  angle = pi/2 - cs
        const float cs0 = __int_as_float(__float_as_int(w0) |
                                         (__float_as_int(dd0) & 0x80000000u));
        const float cs1 = __int_as_float(__float_as_int(w1) |
                                         (__float_as_int(dd1) & 0x80000000u));
        const float cs2 = __int_as_float(__float_as_int(w2) |
                                         (__float_as_int(dd2) & 0x80000000u));
        const float cs3 = __int_as_float(__float_as_int(w3) |
                                         (__float_as_int(dd3) & 0x80000000u));

        S10 = fmaf(t0, cs0, S10);  St0 += t0;
        S11 = fmaf(t1, cs1, S11);  St1 += t1;
        S12 = fmaf(t2, cs2, S12);  St2 += t2;
        S13 = fmaf(t3, cs3, S13);  St3 += t3;

        // rotate (register renames only)
        dx = rx; dy0 = ry0; dy1 = ry1; dy2 = ry2; dy3 = ry3;
    }

    float4 o;
    o.x = fminf(fabsf(fmaf(HPI, St0, -S10)) * INV2PI, 1.0f);
    o.y = fminf(fabsf(fmaf(HPI, St1, -S11)) * INV2PI, 1.0f);
    o.z = fminf(fabsf(fmaf(HPI, St2, -S12)) * INV2PI, 1.0f);
    o.w = fminf(fabsf(fmaf(HPI, St3, -S13)) * INV2PI, 1.0f);
    ((float4*)out)[c * (MSIZE * MSIZE / 4) + gid] = o;
}

extern "C" void kernel_launch(void* const* d_in, const int* in_sizes, int n_in,
                              void* d_out, int out_size)
{
    const float* contour = (const float*)d_in[0];
    float* out = (float*)d_out;

    dim3 grid((MSIZE * MSIZE) / (4 * 128), NCONT);   // 128 x 8 = 1024 blocks
    contour_mask_kernel<<<grid, 128>>>(contour, out);
}

// round 15
// speedup vs baseline: 1.6000x; 1.3924x over previous
#include <cuda_runtime.h>

// Contour_to_mask via exact winding number + analytic band correction.
//
// Identity: sum_k sign(cr_k)*angle_k(exact) = 2*pi*S, S = signed crossing count
// of the vertical ray x=xs, y>ys (in ref's sign convention cr = dy*rx - dx*ry).
// ref_sum = sum tanh(K*cr)*angle differs only where tanh != sign (|cr| < ~9e-5)
// -> out = min(|2*pi*S + C| / 2pi, 1),  C = sum_band (tanh - sign)*angle.
// (t - sign) == 0 exactly for saturated pixels, so slow path needs no masking.
//
// 4 px/thread (same row -> dx, rx, straddle warp-uniform). Scalar body.

#define MSIZE   256
#define KV      64
#define NCONT   8
#define KCONST  100000.0f
#define TBAND   2e-4f                  /* |cr| band: K*cr < 20 covers tanh!=+-1 */

__device__ __forceinline__ float frcp(float x) {
    float r; asm("rcp.approx.f32 %0,%1;" : "=f"(r) : "f"(x)); return r;
}
__device__ __forceinline__ float ftanh(float x) {
    float r; asm("tanh.approx.f32 %0,%1;" : "=f"(r) : "f"(x)); return r;
}

// atan deg-7 minimax on [-1,1] (odd): atan(r) ~= r*(b0 + b1 s + b2 s^2 + b3 s^3)
#define BP0  0.9992150f
#define BP1 -0.3211819f
#define BP2  0.1462766f
#define BP3 -0.0389929f

#define QPI     0.7853981633974483f
#define HPI     1.5707963267948966f
#define TWOPI   6.283185307179586f
#define INV2PI  0.15915494309189535f

__global__ void __launch_bounds__(128, 8) contour_mask_kernel(
    const float* __restrict__ contour,   // [NCONT, KV, 2]
    float* __restrict__ out)             // [NCONT, MSIZE, MSIZE]
{
    __shared__ float2 sv[KV];   // raw (X, Y)

    const int c = blockIdx.y;
    const int t = threadIdx.x;

    if (t < KV) sv[t] = ((const float2*)contour)[c * KV + t];
    __syncthreads();

    const int gid  = blockIdx.x * blockDim.x + t;     // 0 .. 16383
    const int pix0 = gid * 4;
    const float xs  = (float)(pix0 >> 8)  * (1.0f / MSIZE);
    const float yb  = (float)(pix0 & 255) * (1.0f / MSIZE);
    const float ys0 = yb;
    const float ys1 = yb + 1.0f / MSIZE;
    const float ys2 = yb + 2.0f / MSIZE;
    const float ys3 = yb + 3.0f / MSIZE;

    const float2 v0 = sv[0];
    float dx  = v0.x - xs;
    float dy0 = v0.y - ys0;
    float dy1 = v0.y - ys1;
    float dy2 = v0.y - ys2;
    float dy3 = v0.y - ys3;

    float W0 = 0.f, W1 = 0.f, W2 = 0.f, W3 = 0.f;   // fmaf(sdh, pm) sums
    float C0 = 0.f, C1 = 0.f, C2 = 0.f, C3 = 0.f;   // band corrections
    float B  = 0.f;                                  // shared bias (sum sdh)

#pragma unroll 2
    for (int k = 0; k < KV; k++) {
        const int kn = (k + 1) & (KV - 1);
        const float2 q = sv[kn];
        const float rx  = q.x - xs;
        const float ry0 = q.y - ys0;
        const float ry1 = q.y - ys1;
        const float ry2 = q.y - ys2;
        const float ry3 = q.y - ys3;

        const float cr0 = fmaf(dy0, rx, -(dx * ry0));
        const float cr1 = fmaf(dy1, rx, -(dx * ry1));
        const float cr2 = fmaf(dy2, rx, -(dx * ry2));
        const float cr3 = fmaf(dy3, rx, -(dx * ry3));

        // crossing update (warp-uniform straddle; branchless per px)
        // contribution per px: -copysign(1,dx) iff straddle && sign(cr)!=sign(dx)
        //   == fmaf(sdh, pm, .) accumulated, minus shared bias B
        const bool st = (dx > 0.f) != (rx > 0.f);
        const float sdh = st ? __int_as_float(0x3f000000u |
                               (__float_as_int(dx) & 0x80000000u)) : 0.f;
        B += sdh;
        const unsigned dxi = __float_as_int(dx);
        const float pm0 = __int_as_float(0x3f800000u |
                          ((__float_as_int(cr0) ^ dxi) & 0x80000000u));
        const float pm1 = __int_as_float(0x3f800000u |
                          ((__float_as_int(cr1) ^ dxi) & 0x80000000u));
        const float pm2 = __int_as_float(0x3f800000u |
                          ((__float_as_int(cr2) ^ dxi) & 0x80000000u));
        const float pm3 = __int_as_float(0x3f800000u |
                          ((__float_as_int(cr3) ^ dxi) & 0x80000000u));
        W0 = fmaf(sdh, pm0, W0);
        W1 = fmaf(sdh, pm1, W1);
        W2 = fmaf(sdh, pm2, W2);
        W3 = fmaf(sdh, pm3, W3);

        // band: any pixel where tanh(K*cr) may not be exactly +-1
        const float mn = fminf(fminf(fabsf(cr0), fabsf(cr1)),
                               fminf(fabsf(cr2), fabsf(cr3)));
        if (__any_sync(0xffffffffu, mn < TBAND)) {
            const float drs = dx * rx;
            const float cra[4] = {cr0, cr1, cr2, cr3};
            const float rya[4] = {ry0, ry1, ry2, ry3};
            const float dya[4] = {dy0, dy1, dy2, dy3};
            float Ca[4] = {0.f, 0.f, 0.f, 0.f};
#pragma unroll
            for (int j = 0; j < 4; j++) {
                const float cr = cra[j];
                const float dd = fmaf(dya[j], rya[j], drs);
                const float r  = (fabsf(cr) - fabsf(dd)) *
                                 frcp(fabsf(cr) + fabsf(dd));
                const float s  = r * r;
                float p = fmaf(s, BP3, BP2);
                p = fmaf(p, s, BP1);
                p = fmaf(p, s, BP0);
                const float w  = fmaf(-r, p, QPI);
                const float cs = __int_as_float(__float_as_int(w) |
                                 (__float_as_int(dd) & 0x80000000u));
                const float angle = HPI - cs;
                const float th = ftanh(KCONST * cr);
                const float sg = __int_as_float(0x3f800000u |
                                 (__float_as_int(cr) & 0x80000000u));
                Ca[j] = (th - sg) * angle;   // exactly 0 when tanh saturated
            }
            C0 += Ca[0]; C1 += Ca[1]; C2 += Ca[2]; C3 += Ca[3];
        }

        dx = rx; dy0 = ry0; dy1 = ry1; dy2 = ry2; dy3 = ry3;
    }

    const float S0 = W0 - B;
    const float S1 = W1 - B;
    const float S2 = W2 - B;
    const float S3 = W3 - B;

    float4 o;
    o.x = fminf(fabsf(fmaf(TWOPI, S0, C0)) * INV2PI, 1.0f);
    o.y = fminf(fabsf(fmaf(TWOPI, S1, C1)) * INV2PI, 1.0f);
    o.z = fminf(fabsf(fmaf(TWOPI, S2, C2)) * INV2PI, 1.0f);
    o.w = fminf(fabsf(fmaf(TWOPI, S3, C3)) * INV2PI, 1.0f);
    ((float4*)out)[c * (MSIZE * MSIZE / 4) + gid] = o;
}

extern "C" void kernel_launch(void* const* d_in, const int* in_sizes, int n_in,
                              void* d_out, int out_size)
{
    const float* contour = (const float*)d_in[0];
    float* out = (float*)d_out;

    dim3 grid((MSIZE * MSIZE) / (4 * 128), NCONT);   // 128 x 8 = 1024 blocks
    contour_mask_kernel<<<grid, 128>>>(contour, out);
}

// round 16
// speedup vs baseline: 1.9589x; 1.2243x over previous
#include <cuda_runtime.h>

// Contour_to_mask via exact winding number + analytic band correction.
// sum_k sign(cr_k)*angle_k(exact) = 2*pi*S (S = signed ray-crossing count).
// ref differs only where tanh(K*cr) != sign(cr) (|cr| < ~9.4/K).
// out = min(|2*pi*S + C|/2pi, 1), C = sum_band (tanh(K*cr) - sign(cr))*angle.
//
// cr_j is LINEAR in pixel row offset j: cr_j = cr_0 - j*e, e = (rx-dx)*h.
// Crossing accumulation folds to W_j += straddle ? copysign(0.5, cr_j) : 0
// (1 LOP3 + 1 FADD per pixel), bias B += straddle ? copysign(0.5, dx) : 0.
// Slow path: warp-voted on min_j|cr_j| < TBAND, then per-j guarded.

#define MSIZE   256
#define KV      64
#define NCONT   8
#define KCONST  100000.0f
#define H       0.00390625f            /* 1/256 */
#define TBAND   1.5e-4f                /* K*cr < 15; tanh saturates ~9.4 */

__device__ __forceinline__ float frcp(float x) {
    float r; asm("rcp.approx.f32 %0,%1;" : "=f"(r) : "f"(x)); return r;
}
__device__ __forceinline__ float ftanh(float x) {
    float r; asm("tanh.approx.f32 %0,%1;" : "=f"(r) : "f"(x)); return r;
}

// atan deg-7 minimax on [-1,1] (odd)
#define BP0  0.9992150f
#define BP1 -0.3211819f
#define BP2  0.1462766f
#define BP3 -0.0389929f

#define QPI     0.7853981633974483f
#define HPI     1.5707963267948966f
#define TWOPI   6.283185307179586f
#define INV2PI  0.15915494309189535f

__global__ void __launch_bounds__(128, 8) contour_mask_kernel(
    const float* __restrict__ contour,   // [NCONT, KV, 2]
    float* __restrict__ out)             // [NCONT, MSIZE, MSIZE]
{
    __shared__ float2 sv[KV];   // raw (X, Y)

    const int c = blockIdx.y;
    const int t = threadIdx.x;

    if (t < KV) sv[t] = ((const float2*)contour)[c * KV + t];
    __syncthreads();

    const int gid  = blockIdx.x * blockDim.x + t;     // 0 .. 16383
    const int pix0 = gid * 4;
    const float xs  = (float)(pix0 >> 8)  * H;
    const float ys0 = (float)(pix0 & 255) * H;

    const float2 v0 = sv[0];
    float dx  = v0.x - xs;
    float dy0 = v0.y - ys0;

    float W0 = 0.f, W1 = 0.f, W2 = 0.f, W3 = 0.f;   // crossing sums (0.5 steps)
    float C0 = 0.f, C1 = 0.f, C2 = 0.f, C3 = 0.f;   // band corrections
    float B  = 0.f;                                  // shared bias

#pragma unroll 2
    for (int k = 0; k < KV; k++) {
        const int kn = (k + 1) & (KV - 1);
        const float2 q = sv[kn];
        const float rx  = q.x - xs;
        const float ry0 = q.y - ys0;

        // cross products, linear in pixel row index
        const float cr0 = fmaf(dy0, rx, -(dx * ry0));
        const float e   = (rx - dx) * H;
        const float cr1 = cr0 - e;
        const float cr2 = cr1 - e;
        const float cr3 = cr2 - e;

        // crossing update: W_j += straddle ? copysign(0.5, cr_j) : 0
        const bool st = (dx > 0.f) != (rx > 0.f);
        const unsigned hm = st ? 0x3f000000u : 0u;    // 0.5f or +0.0f
        B  += __int_as_float(hm | (__float_as_int(dx)  & 0x80000000u));
        W0 += __int_as_float(hm | (__float_as_int(cr0) & 0x80000000u));
        W1 += __int_as_float(hm | (__float_as_int(cr1) & 0x80000000u));
        W2 += __int_as_float(hm | (__float_as_int(cr2) & 0x80000000u));
        W3 += __int_as_float(hm | (__float_as_int(cr3) & 0x80000000u));

        // band: any pixel where tanh(K*cr) may not be exactly +-1
        const float mn = fminf(fminf(fabsf(cr0), fabsf(cr1)),
                               fminf(fabsf(cr2), fabsf(cr3)));
        if (__any_sync(0xffffffffu, mn < TBAND)) {
            const float drs = dx * rx;
            const float cra[4] = {cr0, cr1, cr2, cr3};
            float Cd[4] = {0.f, 0.f, 0.f, 0.f};
#pragma unroll
            for (int j = 0; j < 4; j++) {
                if (fabsf(cra[j]) < TBAND) {
                    const float dyj = dy0 - (float)j * H;
                    const float ryj = ry0 - (float)j * H;
                    const float cr  = cra[j];
                    const float dd  = fmaf(dyj, ryj, drs);
                    const float r   = (fabsf(cr) - fabsf(dd)) *
                                      frcp(fabsf(cr) + fabsf(dd));
                    const float s   = r * r;
                    float p = fmaf(s, BP3, BP2);
                    p = fmaf(p, s, BP1);
                    p = fmaf(p, s, BP0);
                    const float w  = fmaf(-r, p, QPI);
                    const float cs = __int_as_float(__float_as_int(w) |
                                     (__float_as_int(dd) & 0x80000000u));
                    const float angle = HPI - cs;
                    const float th = ftanh(KCONST * cr);
                    const float sg = __int_as_float(0x3f800000u |
                                     (__float_as_int(cr) & 0x80000000u));
                    Cd[j] = (th - sg) * angle;
                }
            }
            C0 += Cd[0]; C1 += Cd[1]; C2 += Cd[2]; C3 += Cd[3];
        }

        dx = rx; dy0 = ry0;
    }

    float4 o;
    o.x = fminf(fabsf(fmaf(TWOPI, W0 - B, C0)) * INV2PI, 1.0f);
    o.y = fminf(fabsf(fmaf(TWOPI, W1 - B, C1)) * INV2PI, 1.0f);
    o.z = fminf(fabsf(fmaf(TWOPI, W2 - B, C2)) * INV2PI, 1.0f);
    o.w = fminf(fabsf(fmaf(TWOPI, W3 - B, C3)) * INV2PI, 1.0f);
    ((float4*)out)[c * (MSIZE * MSIZE / 4) + gid] = o;
}

extern "C" void kernel_launch(void* const* d_in, const int* in_sizes, int n_in,
                              void* d_out, int out_size)
{
    const float* contour = (const float*)d_in[0];
    float* out = (float*)d_out;

    dim3 grid((MSIZE * MSIZE) / (4 * 128), NCONT);   // 128 x 8 = 1024 blocks
    contour_mask_kernel<<<grid, 128>>>(contour, out);
}

// round 17
// speedup vs baseline: 1.9886x; 1.0152x over previous
#include <cuda_runtime.h>

// Contour_to_mask via exact winding number + analytic band correction.
// sum_k sign(cr_k)*angle_k(exact) = 2*pi*S (S = signed ray-crossing count).
// ref differs only where tanh(K*cr) != sign(cr) (|cr| < ~9.4/K).
// out = min(|2*pi*S + C|/2pi, 1), C = sum_band (tanh(K*cr) - sign(cr))*angle.
//
// cr_j linear in col offset j: cr_j = cr_0 - j*e, e = (rx-dx)*H.
// W_j += straddle ? copysign(0.5, cr_j) : 0;  B += straddle ? copysign(0.5,dx) : 0.
//
// WARP TILING: each warp covers a 4-row x 32-col tile (not a 128x1 strip).
// Tile diameter 0.125 vs 0.5 -> ~4x fewer warp-level band triggers, which
// dominated R16's runtime. Fast-path cost unchanged.

#define MSIZE   256
#define KV      64
#define NCONT   8
#define KCONST  100000.0f
#define H       0.00390625f            /* 1/256 */
#define TBAND   1.5e-4f                /* K*cr < 15; tanh saturates ~9.4 */

__device__ __forceinline__ float frcp(float x) {
    float r; asm("rcp.approx.f32 %0,%1;" : "=f"(r) : "f"(x)); return r;
}
__device__ __forceinline__ float ftanh(float x) {
    float r; asm("tanh.approx.f32 %0,%1;" : "=f"(r) : "f"(x)); return r;
}

// atan deg-7 minimax on [-1,1] (odd)
#define BP0  0.9992150f
#define BP1 -0.3211819f
#define BP2  0.1462766f
#define BP3 -0.0389929f

#define QPI     0.7853981633974483f
#define HPI     1.5707963267948966f
#define TWOPI   6.283185307179586f
#define INV2PI  0.15915494309189535f

__global__ void __launch_bounds__(128, 8) contour_mask_kernel(
    const float* __restrict__ contour,   // [NCONT, KV, 2]
    float* __restrict__ out)             // [NCONT, MSIZE, MSIZE]
{
    __shared__ float2 sv[KV];   // raw (X, Y)

    const int c = blockIdx.y;
    const int t = threadIdx.x;

    if (t < KV) sv[t] = ((const float2*)contour)[c * KV + t];
    __syncthreads();

    // warp-tile mapping: warp = 4 rows x 32 cols; lane -> (row, col-group)
    const int w  = t >> 5;
    const int l  = t & 31;
    const int ti = blockIdx.x * 4 + w;        // tile id 0..511
    const int row  = (ti >> 3) * 4 + (l >> 3);          // 0..255
    const int colb = (ti & 7) * 32 + (l & 7) * 4;       // 0..252, step 4

    const float xs  = (float)row  * H;
    const float ys0 = (float)colb * H;

    const float2 v0 = sv[0];
    float dx  = v0.x - xs;
    float dy0 = v0.y - ys0;

    float W0 = 0.f, W1 = 0.f, W2 = 0.f, W3 = 0.f;   // crossing sums (0.5 steps)
    float C0 = 0.f, C1 = 0.f, C2 = 0.f, C3 = 0.f;   // band corrections
    float B  = 0.f;                                  // per-thread bias

#pragma unroll 2
    for (int k = 0; k < KV; k++) {
        const int kn = (k + 1) & (KV - 1);
        const float2 q = sv[kn];
        const float rx  = q.x - xs;
        const float ry0 = q.y - ys0;

        // cross products, linear in col index
        const float cr0 = fmaf(dy0, rx, -(dx * ry0));
        const float e   = (rx - dx) * H;
        const float cr1 = cr0 - e;
        const float cr2 = cr1 - e;
        const float cr3 = cr2 - e;

        // crossing update: W_j += straddle ? copysign(0.5, cr_j) : 0
        const bool st = (dx > 0.f) != (rx > 0.f);
        const unsigned hm = st ? 0x3f000000u : 0u;    // 0.5f or +0.0f
        B  += __int_as_float(hm | (__float_as_int(dx)  & 0x80000000u));
        W0 += __int_as_float(hm | (__float_as_int(cr0) & 0x80000000u));
        W1 += __int_as_float(hm | (__float_as_int(cr1) & 0x80000000u));
        W2 += __int_as_float(hm | (__float_as_int(cr2) & 0x80000000u));
        W3 += __int_as_float(hm | (__float_as_int(cr3) & 0x80000000u));

        // band: any pixel where tanh(K*cr) may not be exactly +-1
        const float mn = fminf(fminf(fabsf(cr0), fabsf(cr1)),
                               fminf(fabsf(cr2), fabsf(cr3)));
        if (__any_sync(0xffffffffu, mn < TBAND)) {
            const float drs = dx * rx;
            const float cra[4] = {cr0, cr1, cr2, cr3};
            float Cd[4] = {0.f, 0.f, 0.f, 0.f};
#pragma unroll
            for (int j = 0; j < 4; j++) {
                if (fabsf(cra[j]) < TBAND) {
                    const float dyj = dy0 - (float)j * H;
                    const float ryj = ry0 - (float)j * H;
                    const float cr  = cra[j];
                    const float dd  = fmaf(dyj, ryj, drs);
                    const float r   = (fabsf(cr) - fabsf(dd)) *
                                      frcp(fabsf(cr) + fabsf(dd));
                    const float s   = r * r;
                    float p = fmaf(s, BP3, BP2);
                    p = fmaf(p, s, BP1);
                    p = fmaf(p, s, BP0);
                    const float wv = fmaf(-r, p, QPI);
                    const float cs = __int_as_float(__float_as_int(wv) |
                                     (__float_as_int(dd) & 0x80000000u));
                    const float angle = HPI - cs;
                    const float th = ftanh(KCONST * cr);
                    const float sg = __int_as_float(0x3f800000u |
                                     (__float_as_int(cr) & 0x80000000u));
                    Cd[j] = (th - sg) * angle;
                }
            }
            C0 += Cd[0]; C1 += Cd[1]; C2 += Cd[2]; C3 += Cd[3];
        }

        dx = rx; dy0 = ry0;
    }

    float4 o;
    o.x = fminf(fabsf(fmaf(TWOPI, W0 - B, C0)) * INV2PI, 1.0f);
    o.y = fminf(fabsf(fmaf(TWOPI, W1 - B, C1)) * INV2PI, 1.0f);
    o.z = fminf(fabsf(fmaf(TWOPI, W2 - B, C2)) * INV2PI, 1.0f);
    o.w = fminf(fabsf(fmaf(TWOPI, W3 - B, C3)) * INV2PI, 1.0f);
    ((float4*)out)[(c * (MSIZE * MSIZE) + row * MSIZE + colb) >> 2] = o;
}

extern "C" void kernel_launch(void* const* d_in, const int* in_sizes, int n_in,
                              void* d_out, int out_size)
{
    const float* contour = (const float*)d_in[0];
    float* out = (float*)d_out;

    dim3 grid((MSIZE * MSIZE) / (4 * 128), NCONT);   // 128 x 8 = 1024 blocks
    contour_mask_kernel<<<grid, 128>>>(contour, out);
}